// round 9
// baseline (speedup 1.0000x reference)
#include <cuda_runtime.h>
#include <cstdint>

#define BATCH 16
#define CH    256
#define IH    100
#define IW    100
#define NBOX  100
#define RH    40
#define RW    40
#define NCLS  599
#define CPB   2          // channels per CTA in resize/pool kernel
#define GROUPS 8         // output-row groups of 5 rows each
#define SROWS 12         // staged source rows per group (span is <= 12)

// Scratch (no allocations allowed)
__device__ float g_pooled[BATCH * NBOX * CH];   // [B][N][C]  (coalesced reads in k2)
__device__ int   g_start[BATCH * (NCLS + 1)];   // class -> start offset in g_list
__device__ int   g_list[BATCH * NBOX];          // box idx sorted by class (asc n within)

__device__ __forceinline__ void cp_async16(uint32_t dst, const void* src) {
    asm volatile("cp.async.cg.shared.global [%0], [%1], 16;\n" :: "r"(dst), "l"(src));
}
__device__ __forceinline__ uint32_t smem_u32(const void* p) {
    return (uint32_t)__cvta_generic_to_shared(p);
}

// Quantize one box (xyxy, image coords) to the 40x40 grid. Matches
// jnp.round (half-to-even) + clip semantics of the reference.
__device__ __forceinline__ int quantize_box(float4 bb, bool& valid) {
    const float s = 40.0f / 1024.0f;            // exact in fp32
    int x1 = max((int)rintf(bb.x * s), 0);
    int y1 = max((int)rintf(bb.y * s), 0);
    int x2 = min((int)rintf(bb.z * s), RW);
    int y2 = min((int)rintf(bb.w * s), RH);
    valid = (x1 < x2) && (y1 < y2);
    x1 = min(max(x1, 0), RW);  x2 = min(max(x2, 0), RW);
    y1 = min(max(y1, 0), RH);  y2 = min(max(y2, 0), RH);
    return x1 | (y1 << 8) | (x2 << 16) | (y2 << 24);
}

// ---------------------------------------------------------------------------
// Kernel 1: per (b, 2 channels). Source rows are staged through smem with
// coalesced cp.async.cg 16B loads (double-buffered, prefetch next group while
// computing current). Bilinear taps read smem; res -> direct box pooling.
// The cbas==0 CTA of each batch also counting-sorts boxes by class.
// ---------------------------------------------------------------------------
__global__ __launch_bounds__(256) void resize_pool_kernel(
        const float* __restrict__ feat, const float* __restrict__ boxes,
        const int* __restrict__ gt) {
    __shared__ __align__(16) float stage[2][CPB][SROWS * IW];  // 19.2 KB
    __shared__ float res[CPB][RH * RW];         // 12.8 KB
    __shared__ int   s_box[NBOX];
    __shared__ float s_pool[NBOX][CPB];
    __shared__ int   s_cls[NBOX];               // meta CTA only
    __shared__ int   s_cnt[NCLS];               // meta CTA only
    __shared__ int   s_blk[20];

    const int blk  = blockIdx.x;                // 0 .. BATCH*CH/CPB-1
    const int b    = blk / (CH / CPB);
    const int cbas = (blk % (CH / CPB)) * CPB;
    const int tid  = threadIdx.x;
    const bool meta = (cbas == 0);              // uniform across CTA

    const float* __restrict__ in0 = feat + (size_t)(b * CH + cbas) * (IH * IW);
    const float* __restrict__ in1 = in0 + IH * IW;
    const uint32_t stage_base = smem_u32(&stage[0][0][0]);

    // issue coalesced cp.async loads of source-row band for group g into buf
    auto issue_group = [&](int g, int buf) {
        int r0 = (25 * g + 1) >> 1;             // 0,13,25,38,50,63,75,88
        for (int idx = tid; idx < (SROWS * IW / 4) * CPB; idx += 256) {
            int p   = idx / (SROWS * IW / 4);   // plane 0/1
            int f4  = idx % (SROWS * IW / 4);   // float4 index within band
            int row = f4 / (IW / 4);
            int c4  = f4 % (IW / 4);
            const float* src = (p ? in1 : in0) + (r0 + row) * IW + c4 * 4;
            uint32_t dst = stage_base +
                (uint32_t)(((buf * CPB + p) * (SROWS * IW)) + row * IW + c4 * 4) * 4u;
            cp_async16(dst, src);
        }
        asm volatile("cp.async.commit_group;\n");
    };

    // --- quantize this batch's boxes (threads 0..99) ---
    bool v_me = false;
    if (tid < NBOX) {
        float4 bb = __ldg((const float4*)boxes + b * NBOX + tid);
        int pk = quantize_box(bb, v_me);
        s_box[tid] = v_me ? pk : 0;             // invalid -> x1==x2==0
        if (meta) {
            int cls = __ldg(gt + b * NBOX + tid);
            s_cls[tid] = v_me ? cls : -1;
        }
    }

    issue_group(0, 0);

    // --- staged bilinear resize, double-buffered ---
    for (int g = 0; g < GROUPS; g++) {
        int buf = g & 1;
        if (g < GROUPS - 1) issue_group(g + 1, buf ^ 1);
        if (g < GROUPS - 1) asm volatile("cp.async.wait_group 1;\n");
        else                asm volatile("cp.async.wait_group 0;\n");
        __syncthreads();                        // band g visible to all threads

        int r0 = (25 * g + 1) >> 1;
        for (int t = tid; t < 5 * RW * CPB; t += 256) {
            int p   = t / (5 * RW);
            int rem = t % (5 * RW);
            int ly  = rem / RW, ox = rem % RW;
            int oy  = g * 5 + ly;
            float sy = 2.5f * (float)oy + 0.75f;
            float sx = 2.5f * (float)ox + 0.75f;
            int y0 = (int)sy;  float fy = sy - (float)y0;
            int x0 = (int)sx;  float fx = sx - (float)x0;
            const float* st = &stage[buf][p][(y0 - r0) * IW + x0];
            float v00 = st[0],  v01 = st[1];
            float v10 = st[IW], v11 = st[IW + 1];
            float gx0 = 1.0f - fx, gy0 = 1.0f - fy;
            res[p][oy * RW + ox] =
                gy0 * (gx0 * v00 + fx * v01) + fy * (gx0 * v10 + fx * v11);
        }
        __syncthreads();                        // buf free for group g+2
    }

    // --- direct box-average pooling: thread = (plane, box) ---
    if (tid < NBOX * CPB) {
        int n = tid % NBOX;
        int p = tid / NBOX;
        int pk = s_box[n];
        int x1 = pk & 0xFF, y1 = (pk >> 8) & 0xFF;
        int x2 = (pk >> 16) & 0xFF, y2 = (pk >> 24) & 0xFF;
        float out = 0.0f;
        if (x1 < x2) {                          // valid (invalid stored as 0)
            float s = 0.0f;
            const float* r = res[p];
            for (int y = y1; y < y2; y++) {
                float rs = 0.0f;
                for (int x = x1; x < x2; x++) rs += r[y * RW + x];
                s += rs;
            }
            out = s / (float)((y2 - y1) * (x2 - x1));
        }
        s_pool[n][p] = out;
    }
    __syncthreads();

    // --- transposed write: one float2 per box into [B][N][C] ---
    if (tid < NBOX) {
        float2 v2 = make_float2(s_pool[tid][0], s_pool[tid][1]);
        *(float2*)(g_pooled + (size_t)(b * NBOX + tid) * CH + cbas) = v2;
    }

    // --- meta CTA only: counting-sort boxes by class (deterministic) ---
    if (meta) {
        for (int i = tid; i < NCLS; i += 256) s_cnt[i] = 0;
        __syncthreads();
        if (tid < NBOX && s_cls[tid] >= 0)
            atomicAdd(&s_cnt[s_cls[tid]], 1);   // histogram
        __syncthreads();
        if (tid < 19) {                          // group sums (19 x 32)
            int s = 0;
            for (int j = 0; j < 32; j++) {
                int c = tid * 32 + j;
                if (c < NCLS) s += s_cnt[c];
            }
            s_blk[tid] = s;
        }
        __syncthreads();
        if (tid == 0) {
            int r = 0;
            for (int w = 0; w < 19; w++) { int t = s_blk[w]; s_blk[w] = r; r += t; }
            s_blk[19] = r;                      // total valid boxes
        }
        __syncthreads();
        if (tid < 19) {
            int r = s_blk[tid];
            for (int j = 0; j < 32; j++) {
                int c = tid * 32 + j;
                if (c < NCLS) { int t = s_cnt[c]; s_cnt[c] = r; r += t; }  // -> offsets
            }
        }
        __syncthreads();
        for (int i = tid; i < NCLS; i += 256)
            g_start[b * (NCLS + 1) + i] = s_cnt[i];
        if (tid == 0)
            g_start[b * (NCLS + 1) + NCLS] = s_blk[19];
        // scatter: rank = #{m<n with same class} (deterministic ascending order)
        if (tid < NBOX && s_cls[tid] >= 0) {
            int c = s_cls[tid];
            int rank = 0;
            for (int m = 0; m < tid; m++) rank += (s_cls[m] == c);
            g_list[b * NBOX + s_cnt[c] + rank] = tid;
        }
    }
}

// ---------------------------------------------------------------------------
// Kernel 2: scatter-mean, barrier-free (unchanged from R8 — measured 7.9us).
// One 64-thread group per class; thread = float4 channel-quad.
// ---------------------------------------------------------------------------
__global__ __launch_bounds__(256) void class_mean_kernel(float* __restrict__ out) {
    const int t   = threadIdx.x;
    const int cls = blockIdx.x * 4 + (t >> 6);
    const int q   = t & 63;
    const int b   = blockIdx.y;
    if (cls >= NCLS) return;

    const int* sp = &g_start[b * (NCLS + 1) + cls];
    int st = __ldg(sp);
    int en = __ldg(sp + 1);

    float4 acc = make_float4(0.0f, 0.0f, 0.0f, 0.0f);
    if (en > st) {
        const float4* __restrict__ pool =
            (const float4*)(g_pooled + (size_t)b * NBOX * CH) + q;
        for (int k = st; k < en; k++) {          // ascending n within class
            int n = __ldg(&g_list[b * NBOX + k]);
            float4 v = __ldg(pool + (size_t)n * (CH / 4));
            acc.x += v.x;  acc.y += v.y;  acc.z += v.z;  acc.w += v.w;
        }
        float inv = 1.0f / (float)(en - st);
        acc.x *= inv;  acc.y *= inv;  acc.z *= inv;  acc.w *= inv;
    }
    ((float4*)(out + (size_t)(b * NCLS + cls) * CH))[q] = acc;
}

// ---------------------------------------------------------------------------
extern "C" void kernel_launch(void* const* d_in, const int* in_sizes, int n_in,
                              void* d_out, int out_size) {
    const float* feat  = (const float*)d_in[0];   // [16,256,100,100] f32
    const float* boxes = (const float*)d_in[1];   // [16,100,4] f32
    const int*   gt    = (const int*)d_in[2];     // [16,100] i32
    float* out = (float*)d_out;                   // [16,599,256] f32

    resize_pool_kernel<<<BATCH * (CH / CPB), 256>>>(feat, boxes, gt);
    dim3 g2((NCLS + 3) / 4, BATCH);               // 150 x 16
    class_mean_kernel<<<g2, 256>>>(out);
}

// round 10
// speedup vs baseline: 1.0976x; 1.0976x over previous
#include <cuda_runtime.h>

#define BATCH 16
#define CH    256
#define IH    100
#define IW    100
#define NBOX  100
#define RH    40
#define RW    40
#define NCLS  599
#define CPB   2          // channels per CTA in resize/pool kernel (known-good)
#define K2_CLS 4         // classes per 64-thread group in class_mean kernel

// Scratch (no allocations allowed)
__device__ float g_pooled[BATCH * NBOX * CH];   // [B][N][C]  (coalesced reads in k2)
__device__ int   g_start[BATCH * (NCLS + 1)];   // class -> start offset in g_list
__device__ int   g_list[BATCH * NBOX];          // box idx sorted by class (asc n within)

// Quantize one box (xyxy, image coords) to the 40x40 grid. Matches
// jnp.round (half-to-even) + clip semantics of the reference.
__device__ __forceinline__ int quantize_box(float4 bb, bool& valid) {
    const float s = 40.0f / 1024.0f;            // exact in fp32
    int x1 = max((int)rintf(bb.x * s), 0);
    int y1 = max((int)rintf(bb.y * s), 0);
    int x2 = min((int)rintf(bb.z * s), RW);
    int y2 = min((int)rintf(bb.w * s), RH);
    valid = (x1 < x2) && (y1 < y2);
    x1 = min(max(x1, 0), RW);  x2 = min(max(x2, 0), RW);
    y1 = min(max(y1, 0), RH);  y2 = min(max(y2, 0), RH);
    return x1 | (y1 << 8) | (x2 << 16) | (y2 << 24);
}

// ---------------------------------------------------------------------------
// Kernel 1 (R6-proven body): per (b, 2 channels) — direct-__ldg bilinear
// 100->40 resize into smem, then direct box-sum pooling. The cbas==0 CTA of
// each batch also counting-sorts boxes by class into g_start / g_list
// (deterministic, ascending-n within each class).
// ---------------------------------------------------------------------------
__global__ __launch_bounds__(256) void resize_pool_kernel(
        const float* __restrict__ feat, const float* __restrict__ boxes,
        const int* __restrict__ gt) {
    __shared__ float res[CPB][RH * RW];         // 12.8 KB
    __shared__ int   s_box[NBOX];               // packed x1,y1,x2,y2 (0 if invalid)
    __shared__ float s_pool[NBOX][CPB];         // staged for float2 writes
    __shared__ int   s_cls[NBOX];               // valid ? cls : -1 (meta CTA)
    __shared__ int   s_cnt[NCLS];               // histogram -> offsets (meta CTA)
    __shared__ int   s_blk[20];

    const int blk  = blockIdx.x;                // 0 .. BATCH*CH/CPB-1
    const int b    = blk / (CH / CPB);
    const int cbas = (blk % (CH / CPB)) * CPB;
    const int tid  = threadIdx.x;
    const bool meta = (cbas == 0);              // uniform across CTA

    // --- quantize this batch's boxes (threads 0..99) ---
    bool v_me = false;
    if (tid < NBOX) {
        float4 bb = __ldg((const float4*)boxes + b * NBOX + tid);
        int pk = quantize_box(bb, v_me);
        s_box[tid] = v_me ? pk : 0;             // invalid -> x1==x2==0
        if (meta) {
            int cls = __ldg(gt + b * NBOX + tid);
            s_cls[tid] = v_me ? cls : -1;
        }
    }

    // --- bilinear resize (half-pixel centers): src = 2.5*dst + 0.75 ---
    const float* __restrict__ in0 = feat + (size_t)(b * CH + cbas) * (IH * IW);
    const float* __restrict__ in1 = in0 + IH * IW;
    for (int i = tid; i < RH * RW; i += 256) {
        int oy = i / RW, ox = i % RW;
        float sy = 2.5f * (float)oy + 0.75f;    // frac is exactly .75 or .25
        float sx = 2.5f * (float)ox + 0.75f;
        int y0 = (int)sy;  float fy = sy - (float)y0;
        int x0 = (int)sx;  float fx = sx - (float)x0;
        int off = y0 * IW + x0;
        float gx0 = 1.0f - fx, gy0 = 1.0f - fy;
        float a00 = __ldg(in0 + off),      a01 = __ldg(in0 + off + 1);
        float a10 = __ldg(in0 + off + IW), a11 = __ldg(in0 + off + IW + 1);
        float b00 = __ldg(in1 + off),      b01 = __ldg(in1 + off + 1);
        float b10 = __ldg(in1 + off + IW), b11 = __ldg(in1 + off + IW + 1);
        res[0][i] = gy0 * (gx0 * a00 + fx * a01) + fy * (gx0 * a10 + fx * a11);
        res[1][i] = gy0 * (gx0 * b00 + fx * b01) + fy * (gx0 * b10 + fx * b11);
    }
    __syncthreads();

    // --- direct box-average pooling: thread = (plane, box) ---
    if (tid < NBOX * CPB) {
        int n = tid % NBOX;
        int p = tid / NBOX;
        int pk = s_box[n];
        int x1 = pk & 0xFF, y1 = (pk >> 8) & 0xFF;
        int x2 = (pk >> 16) & 0xFF, y2 = (pk >> 24) & 0xFF;
        float out = 0.0f;
        if (x1 < x2) {                          // valid (invalid stored as 0)
            float s = 0.0f;
            const float* r = res[p];
            for (int y = y1; y < y2; y++) {
                float rs = 0.0f;
                for (int x = x1; x < x2; x++) rs += r[y * RW + x];
                s += rs;
            }
            out = s / (float)((y2 - y1) * (x2 - x1));
        }
        s_pool[n][p] = out;
    }
    __syncthreads();

    // --- transposed write: one float2 per box into [B][N][C] ---
    if (tid < NBOX) {
        float2 v2 = make_float2(s_pool[tid][0], s_pool[tid][1]);
        *(float2*)(g_pooled + (size_t)(b * NBOX + tid) * CH + cbas) = v2;
    }

    // --- meta CTA only: counting-sort boxes by class (deterministic) ---
    if (meta) {
        for (int i = tid; i < NCLS; i += 256) s_cnt[i] = 0;
        __syncthreads();
        if (tid < NBOX && s_cls[tid] >= 0)
            atomicAdd(&s_cnt[s_cls[tid]], 1);   // histogram
        __syncthreads();
        if (tid < 19) {                          // group sums (19 x 32)
            int s = 0;
            for (int j = 0; j < 32; j++) {
                int c = tid * 32 + j;
                if (c < NCLS) s += s_cnt[c];
            }
            s_blk[tid] = s;
        }
        __syncthreads();
        if (tid == 0) {
            int r = 0;
            for (int w = 0; w < 19; w++) { int t = s_blk[w]; s_blk[w] = r; r += t; }
            s_blk[19] = r;                      // total valid boxes
        }
        __syncthreads();
        if (tid < 19) {
            int r = s_blk[tid];
            for (int j = 0; j < 32; j++) {
                int c = tid * 32 + j;
                if (c < NCLS) { int t = s_cnt[c]; s_cnt[c] = r; r += t; }  // -> offsets
            }
        }
        __syncthreads();
        for (int i = tid; i < NCLS; i += 256)
            g_start[b * (NCLS + 1) + i] = s_cnt[i];
        if (tid == 0)
            g_start[b * (NCLS + 1) + NCLS] = s_blk[19];
        // scatter: rank = #{m<n with same class} (deterministic ascending order)
        if (tid < NBOX && s_cls[tid] >= 0) {
            int c = s_cls[tid];
            int rank = 0;
            for (int m = 0; m < tid; m++) rank += (s_cls[m] == c);
            g_list[b * NBOX + s_cnt[c] + rank] = tid;
        }
    }
}

// ---------------------------------------------------------------------------
// Kernel 2: scatter-mean, barrier-free, 4 classes per 64-thread group
// (16 classes per CTA; grid 38x16 ~= single wave). Boundary loads for all
// 4 classes issue in parallel up-front (one latency). Empty classes -> one
// STG.128 of zeros. Non-empty: walk presorted g_list segment (ascending n
// == segment_sum order) with float4 gathers. No smem, no __syncthreads.
// ---------------------------------------------------------------------------
__global__ __launch_bounds__(256) void class_mean_kernel(float* __restrict__ out) {
    const int t  = threadIdx.x;
    const int c0 = (blockIdx.x * 4 + (t >> 6)) * K2_CLS;   // first class of group
    const int q  = t & 63;                                 // channel quad 0..63
    const int b  = blockIdx.y;
    if (c0 >= NCLS) return;

    // boundary offsets for the 4 classes: 5 parallel uniform loads
    const int* sp = &g_start[b * (NCLS + 1) + c0];
    int s0 = __ldg(sp + 0);
    int s1 = (c0 + 1 <= NCLS) ? __ldg(sp + 1) : s0;
    int s2 = (c0 + 2 <= NCLS) ? __ldg(sp + 2) : s1;
    int s3 = (c0 + 3 <= NCLS) ? __ldg(sp + 3) : s2;
    int s4 = (c0 + 4 <= NCLS) ? __ldg(sp + 4) : s3;
    int st[K2_CLS + 1] = {s0, s1, s2, s3, s4};

    const float4* __restrict__ pool =
        (const float4*)(g_pooled + (size_t)b * NBOX * CH) + q;
    const int* __restrict__ list = &g_list[b * NBOX];
    float4* __restrict__ obase =
        (float4*)(out + (size_t)(b * NCLS + c0) * CH) + q;

    #pragma unroll
    for (int j = 0; j < K2_CLS; j++) {
        int cls = c0 + j;
        if (cls >= NCLS) break;
        int a = st[j], e = st[j + 1];
        float4 acc = make_float4(0.0f, 0.0f, 0.0f, 0.0f);
        if (e > a) {
            for (int k = a; k < e; k++) {        // ascending n within class
                int n = __ldg(list + k);
                float4 v = __ldg(pool + (size_t)n * (CH / 4));
                acc.x += v.x;  acc.y += v.y;  acc.z += v.z;  acc.w += v.w;
            }
            float inv = 1.0f / (float)(e - a);
            acc.x *= inv;  acc.y *= inv;  acc.z *= inv;  acc.w *= inv;
        }
        obase[(size_t)j * (CH / 4)] = acc;
    }
}

// ---------------------------------------------------------------------------
extern "C" void kernel_launch(void* const* d_in, const int* in_sizes, int n_in,
                              void* d_out, int out_size) {
    const float* feat  = (const float*)d_in[0];   // [16,256,100,100] f32
    const float* boxes = (const float*)d_in[1];   // [16,100,4] f32
    const int*   gt    = (const int*)d_in[2];     // [16,100] i32
    float* out = (float*)d_out;                   // [16,599,256] f32

    resize_pool_kernel<<<BATCH * (CH / CPB), 256>>>(feat, boxes, gt);
    dim3 g2((NCLS + 4 * K2_CLS - 1) / (4 * K2_CLS), BATCH);   // 38 x 16
    class_mean_kernel<<<g2, 256>>>(out);
}